// round 8
// baseline (speedup 1.0000x reference)
#include <cuda_runtime.h>
#include <cstdint>

// XSimGCL / LightGCN on GB300 (sm_103a) — slotted-CSR formulation.
// R7 post-mortem: spmm layers ~ at L2 gather roofline; CSR build overhead
// (degree + 3-pass scan + launch gaps ~30us) removed via fixed 128-slot rows.
// Layer-2 now predicated on flagged ∪ neighbors(flagged) (~80% of rows).

#define NUM_USERS 100000
#define NUM_ITEMS 50000
#define NTOT      (NUM_USERS + NUM_ITEMS)   // 150000
#define D4        16                        // float4s per 64-dim row
#define BATCH     4096
#define MAXROWS   8192
#define CAP       128                       // slots per row (max deg ~67 here)

// Scratch (allocation-free rule: __device__ globals; device-code refs only).
__device__ float4   g_X1[NTOT * D4];
__device__ float4   g_X2[NTOT * D4];
__device__ float4   g_X3[NTOT * D4];
__device__ int      g_pos[NTOT];
__device__ int2     g_slots[(size_t)NTOT * CAP];   // {col, float_as_int(val)}
__device__ unsigned g_bitmap [(NTOT + 31) / 32];   // flagged (layer-3 outputs)
__device__ unsigned g_bitmap2[(NTOT + 31) / 32];   // flagged ∪ N(flagged) (layer-2)
__device__ int      g_rowlist[MAXROWS];
__device__ int      g_nrows;

// ---------------------------------------------------------------------------
__global__ void zero_kernel() {
    int i = blockIdx.x * blockDim.x + threadIdx.x;
    if (i < NTOT) g_pos[i] = 0;
    if (i < (NTOT + 31) / 32) { g_bitmap[i] = 0u; g_bitmap2[i] = 0u; }
    if (i == 0) g_nrows = 0;
}

// Mark rows whose layer-3 output is needed; compact unique rows; seed bitmap2.
__global__ void mark_kernel(const int* __restrict__ uid,
                            const int* __restrict__ iid) {
    int i = blockIdx.x * blockDim.x + threadIdx.x;
    if (i >= BATCH) return;
    unsigned r[2];
    r[0] = (unsigned)uid[i];
    r[1] = (unsigned)iid[i] + NUM_USERS;
    #pragma unroll
    for (int k = 0; k < 2; k++) {
        if (r[k] < NTOT) {
            unsigned bit = 1u << (r[k] & 31);
            unsigned old = atomicOr(&g_bitmap[r[k] >> 5], bit);
            atomicOr(&g_bitmap2[r[k] >> 5], bit);
            if (!(old & bit)) {
                int p = atomicAdd(&g_nrows, 1);
                if (p < MAXROWS) g_rowlist[p] = (int)r[k];
            }
        }
    }
}

// ---------------------------------------------------------------------------
// Scatter edges into fixed-capacity row slots (no degree pass, no scan).
// Fused: if the destination row is flagged, mark its column in bitmap2
// (columns of flagged rows = rows whose X2 the layer-3 gather will read).
// ---------------------------------------------------------------------------
__global__ void scatter_kernel(const float* __restrict__ vals,
                               const int*   __restrict__ rows,
                               const int*   __restrict__ cols,
                               int ne) {
    int e = blockIdx.x * blockDim.x + threadIdx.x;
    if (e >= ne) return;
    unsigned r = (unsigned)__ldg(&rows[e]);
    if (r >= NTOT) return;
    int   c = __ldg(&cols[e]);
    float v = __ldg(&vals[e]);
    int p = atomicAdd(&g_pos[r], 1);
    if (p < CAP) g_slots[(size_t)r * CAP + p] = make_int2(c, __float_as_int(v));
    if ((g_bitmap[r >> 5] >> (r & 31)) & 1u) {
        unsigned uc = (unsigned)c;
        if (uc < NTOT) atomicOr(&g_bitmap2[uc >> 5], 1u << (uc & 31));
    }
}

// ---------------------------------------------------------------------------
// Slotted-CSR SpMM: one 16-lane group per row, register acc, single store.
// LAYER 0: src = (user_emb|item_emb) direct, dst = X1 (all rows)
// LAYER 1: X1 -> X2, only rows in bitmap2 (flagged ∪ N(flagged))
// LAYER 2: X2 -> X3, only compacted g_rowlist
// ---------------------------------------------------------------------------
template <int LAYER>
__device__ __forceinline__ float4 gather(const float4* __restrict__ ue,
                                         const float4* __restrict__ ie,
                                         const float4* __restrict__ src,
                                         int c, int l) {
    if (LAYER == 0)
        return (c < NUM_USERS) ? __ldg(&ue[c * D4 + l])
                               : __ldg(&ie[(c - NUM_USERS) * D4 + l]);
    return __ldg(&src[c * D4 + l]);
}

template <int LAYER>
__global__ void __launch_bounds__(256)
spmm_kernel(const float4* __restrict__ ue,
            const float4* __restrict__ ie) {
    int gid = blockIdx.x * blockDim.x + threadIdx.x;
    int g = gid >> 4;
    int l = gid & 15;

    int r;
    if (LAYER == 2) {
        if (g >= g_nrows) return;
        r = g_rowlist[g];
    } else {
        if (g >= NTOT) return;
        r = g;
        if (LAYER == 1) {
            if (!((g_bitmap2[r >> 5] >> (r & 31)) & 1u)) return;
        }
    }

    int deg = __ldg(&g_pos[r]);
    deg = (deg < CAP) ? deg : CAP;
    const int2* __restrict__ seg = &g_slots[(size_t)r * CAP];

    const float4* __restrict__ src = (LAYER == 1) ? g_X1 : g_X2;
    float4 acc = make_float4(0.f, 0.f, 0.f, 0.f);

    int j = 0;
    for (; j + 3 < deg; j += 4) {          // 4 gathers in flight per group
        int2 c0 = __ldg(&seg[j]);
        int2 c1 = __ldg(&seg[j + 1]);
        int2 c2 = __ldg(&seg[j + 2]);
        int2 c3 = __ldg(&seg[j + 3]);
        float4 x0 = gather<LAYER>(ue, ie, src, c0.x, l);
        float4 x1 = gather<LAYER>(ue, ie, src, c1.x, l);
        float4 x2 = gather<LAYER>(ue, ie, src, c2.x, l);
        float4 x3 = gather<LAYER>(ue, ie, src, c3.x, l);
        float v0 = __int_as_float(c0.y), v1 = __int_as_float(c1.y);
        float v2 = __int_as_float(c2.y), v3 = __int_as_float(c3.y);
        acc.x += v0 * x0.x + v1 * x1.x + v2 * x2.x + v3 * x3.x;
        acc.y += v0 * x0.y + v1 * x1.y + v2 * x2.y + v3 * x3.y;
        acc.z += v0 * x0.z + v1 * x1.z + v2 * x2.z + v3 * x3.z;
        acc.w += v0 * x0.w + v1 * x1.w + v2 * x2.w + v3 * x3.w;
    }
    for (; j < deg; j++) {
        int2 c0 = __ldg(&seg[j]);
        float4 x0 = gather<LAYER>(ue, ie, src, c0.x, l);
        float v0 = __int_as_float(c0.y);
        acc.x += v0 * x0.x; acc.y += v0 * x0.y;
        acc.z += v0 * x0.z; acc.w += v0 * x0.w;
    }

    float4* __restrict__ dst = (LAYER == 0) ? g_X1 : (LAYER == 1) ? g_X2 : g_X3;
    dst[r * D4 + l] = acc;
}

// ---------------------------------------------------------------------------
// Readout: out[b] = dot((X1+X2+X3)[u], (X1+X2+X3)[i+NU]) / 9
// ---------------------------------------------------------------------------
__global__ void dot_kernel(const int* __restrict__ uid,
                           const int* __restrict__ iid,
                           float* __restrict__ out) {
    int gid = blockIdx.x * blockDim.x + threadIdx.x;
    int b = gid >> 4;
    int l = gid & 15;
    if (b >= BATCH) return;

    unsigned ur = (unsigned)__ldg(&uid[b]);
    unsigned ir = (unsigned)__ldg(&iid[b]) + NUM_USERS;
    float d = 0.f;

    if (ur < NTOT && ir < NTOT) {
        int uo = (int)ur * D4 + l;
        int io = (int)ir * D4 + l;
        float4 a1 = g_X1[uo], a2 = g_X2[uo], a3 = g_X3[uo];
        float4 b1 = g_X1[io], b2 = g_X2[io], b3 = g_X3[io];
        float fux = a1.x + a2.x + a3.x, fuy = a1.y + a2.y + a3.y;
        float fuz = a1.z + a2.z + a3.z, fuw = a1.w + a2.w + a3.w;
        float fix = b1.x + b2.x + b3.x, fiy = b1.y + b2.y + b3.y;
        float fiz = b1.z + b2.z + b3.z, fiw = b1.w + b2.w + b3.w;
        d = fux * fix + fuy * fiy + fuz * fiz + fuw * fiw;
    }

    #pragma unroll
    for (int off = 8; off > 0; off >>= 1)
        d += __shfl_down_sync(0xffffffffu, d, off, 16);

    if (l == 0) out[b] = d * (1.0f / 9.0f);
}

// ---------------------------------------------------------------------------
extern "C" void kernel_launch(void* const* d_in, const int* in_sizes, int n_in,
                              void* d_out, int out_size) {
    const float4* user_emb = (const float4*)d_in[0];   // [100000,64] f32
    const float4* item_emb = (const float4*)d_in[1];   // [50000,64]  f32
    const float*  vals     = (const float*) d_in[2];   // [2E] f32
    const int*    rows     = (const int*)   d_in[3];   // [2E] i32
    const int*    cols     = (const int*)   d_in[4];   // [2E] i32
    const int*    uid      = (const int*)   d_in[5];   // [4096] i32
    const int*    iid      = (const int*)   d_in[6];   // [4096] i32
    float*        out      = (float*)d_out;            // [4096] f32

    const int ne = in_sizes[2];

    zero_kernel<<<(NTOT + 255) / 256, 256>>>();
    mark_kernel<<<(BATCH + 255) / 256, 256>>>(uid, iid);

    scatter_kernel<<<(ne + 255) / 256, 256>>>(vals, rows, cols, ne);

    int t_dense = NTOT * D4;
    spmm_kernel<0><<<(t_dense + 255) / 256, 256>>>(user_emb, item_emb);
    spmm_kernel<1><<<(t_dense + 255) / 256, 256>>>(user_emb, item_emb);
    spmm_kernel<2><<<(MAXROWS * 16 + 255) / 256, 256>>>(user_emb, item_emb);

    dot_kernel<<<(BATCH * 16 + 255) / 256, 256>>>(uid, iid, out);
}

// round 10
// speedup vs baseline: 1.2485x; 1.2485x over previous
#include <cuda_runtime.h>
#include <cstdint>

// XSimGCL / LightGCN on GB300 (sm_103a) — compact CSR (R7 layout, reverted
// from R8's slotted experiment: 153MB sparse slots broke L2 residency and
// 4-wide unroll cost occupancy). Kept from R8: layer-1 predication on
// bitmap2 = flagged ∪ N(flagged), marked for free inside scatter.
// (R9 bench was an infra failure — resubmitting unchanged.)

#define NUM_USERS 100000
#define NUM_ITEMS 50000
#define NTOT      (NUM_USERS + NUM_ITEMS)   // 150000
#define D4        16                        // float4s per 64-dim row
#define BATCH     4096
#define MAXE      4200000                   // >= 2*NUM_BASE_EDGES
#define MAXROWS   8192
#define SCAN_B    256
#define NBLK      ((NTOT + SCAN_B - 1) / SCAN_B)   // 586

// Scratch (allocation-free rule: __device__ globals; device-code refs only).
__device__ float4   g_X1[NTOT * D4];
__device__ float4   g_X2[NTOT * D4];
__device__ float4   g_X3[NTOT * D4];
__device__ int      g_cnt[NTOT];
__device__ int      g_off[NTOT + 1];
__device__ int      g_pos[NTOT];
__device__ int      g_part[1024];           // >= NBLK
__device__ int2     g_cva[MAXE];            // packed {col, float_as_int(val)}
__device__ unsigned g_bitmap [(NTOT + 31) / 32];   // flagged (layer-3 outputs)
__device__ unsigned g_bitmap2[(NTOT + 31) / 32];   // flagged ∪ N(flagged)
__device__ int      g_rowlist[MAXROWS];
__device__ int      g_nrows;

// ---------------------------------------------------------------------------
__global__ void zero_kernel() {
    int i = blockIdx.x * blockDim.x + threadIdx.x;
    if (i < NTOT) g_cnt[i] = 0;
    if (i < (NTOT + 31) / 32) { g_bitmap[i] = 0u; g_bitmap2[i] = 0u; }
    if (i == 0) g_nrows = 0;
}

// Mark rows whose layer-3 output is needed; compact unique rows; seed bitmap2.
__global__ void mark_kernel(const int* __restrict__ uid,
                            const int* __restrict__ iid) {
    int i = blockIdx.x * blockDim.x + threadIdx.x;
    if (i >= BATCH) return;
    unsigned r[2];
    r[0] = (unsigned)uid[i];
    r[1] = (unsigned)iid[i] + NUM_USERS;
    #pragma unroll
    for (int k = 0; k < 2; k++) {
        if (r[k] < NTOT) {
            unsigned bit = 1u << (r[k] & 31);
            unsigned old = atomicOr(&g_bitmap[r[k] >> 5], bit);
            atomicOr(&g_bitmap2[r[k] >> 5], bit);
            if (!(old & bit)) {
                int p = atomicAdd(&g_nrows, 1);
                if (p < MAXROWS) g_rowlist[p] = (int)r[k];
            }
        }
    }
}

// ---------------------------------------------------------------------------
// CSR build: histogram -> 3-pass parallel exclusive scan -> scatter.
// ---------------------------------------------------------------------------
__global__ void degree_kernel(const int* __restrict__ rows, int ne) {
    int e = blockIdx.x * blockDim.x + threadIdx.x;
    if (e >= ne) return;
    unsigned r = (unsigned)__ldg(&rows[e]);
    if (r < NTOT) atomicAdd(&g_cnt[r], 1);
}

__global__ void scan_reduce_kernel() {
    __shared__ int sh[SCAN_B];
    int idx = blockIdx.x * SCAN_B + threadIdx.x;
    sh[threadIdx.x] = (idx < NTOT) ? g_cnt[idx] : 0;
    __syncthreads();
    #pragma unroll
    for (int off = SCAN_B / 2; off > 0; off >>= 1) {
        if (threadIdx.x < off) sh[threadIdx.x] += sh[threadIdx.x + off];
        __syncthreads();
    }
    if (threadIdx.x == 0) g_part[blockIdx.x] = sh[0];
}

__global__ void scan_partials_kernel() {
    __shared__ int sh[1024];
    int tid = threadIdx.x;
    int v = (tid < NBLK) ? g_part[tid] : 0;
    sh[tid] = v;
    __syncthreads();
    for (int off = 1; off < 1024; off <<= 1) {
        int t = (tid >= off) ? sh[tid - off] : 0;
        __syncthreads();
        sh[tid] += t;
        __syncthreads();
    }
    if (tid < NBLK) g_part[tid] = sh[tid] - v;   // exclusive
    if (tid == NBLK - 1) g_off[NTOT] = sh[tid];
}

__global__ void scan_final_kernel() {
    __shared__ int sh[SCAN_B];
    int idx = blockIdx.x * SCAN_B + threadIdx.x;
    int c = (idx < NTOT) ? g_cnt[idx] : 0;
    sh[threadIdx.x] = c;
    __syncthreads();
    #pragma unroll
    for (int off = 1; off < SCAN_B; off <<= 1) {
        int t = (threadIdx.x >= off) ? sh[threadIdx.x - off] : 0;
        __syncthreads();
        sh[threadIdx.x] += t;
        __syncthreads();
    }
    if (idx < NTOT) {
        int off = g_part[blockIdx.x] + sh[threadIdx.x] - c;   // exclusive
        g_off[idx] = off;
        g_pos[idx] = off;
    }
}

// Scatter into compact CSR. Fused: columns of flagged rows -> bitmap2
// (those rows' X2 is gathered by layer 3, so layer 1 must produce them).
__global__ void scatter_kernel(const float* __restrict__ vals,
                               const int*   __restrict__ rows,
                               const int*   __restrict__ cols,
                               int ne) {
    int e = blockIdx.x * blockDim.x + threadIdx.x;
    if (e >= ne) return;
    unsigned r = (unsigned)__ldg(&rows[e]);
    if (r >= NTOT) return;
    int   c = __ldg(&cols[e]);
    float v = __ldg(&vals[e]);
    int p = atomicAdd(&g_pos[r], 1);
    if (p < MAXE) g_cva[p] = make_int2(c, __float_as_int(v));
    if ((g_bitmap[r >> 5] >> (r & 31)) & 1u) {
        unsigned uc = (unsigned)c;
        if (uc < NTOT) atomicOr(&g_bitmap2[uc >> 5], 1u << (uc & 31));
    }
}

// ---------------------------------------------------------------------------
// CSR SpMM: one 16-lane group per row, register accumulate, single store.
// LAYER 0: src = (user_emb|item_emb) direct, dst = X1 (all rows)
// LAYER 1: X1 -> X2, only rows in bitmap2 (flagged ∪ N(flagged), ~80%)
// LAYER 2: X2 -> X3, only compacted g_rowlist
// ---------------------------------------------------------------------------
template <int LAYER>
__global__ void __launch_bounds__(256)
spmm_csr_kernel(const float4* __restrict__ ue,
                const float4* __restrict__ ie) {
    int gid = blockIdx.x * blockDim.x + threadIdx.x;
    int g = gid >> 4;
    int l = gid & 15;

    int r;
    if (LAYER == 2) {
        if (g >= g_nrows) return;
        r = g_rowlist[g];
    } else {
        if (g >= NTOT) return;
        r = g;
        if (LAYER == 1) {
            if (!((g_bitmap2[r >> 5] >> (r & 31)) & 1u)) return;
        }
    }

    int beg = __ldg(&g_off[r]);
    int end = __ldg(&g_off[r + 1]);

    const float4* __restrict__ src = (LAYER == 1) ? g_X1 : g_X2;  // unused L0
    float4 acc = make_float4(0.f, 0.f, 0.f, 0.f);

    int j = beg;
    for (; j + 1 < end; j += 2) {       // 2 gathers in flight per group
        int2 ca = __ldg(&g_cva[j]);
        int2 cb = __ldg(&g_cva[j + 1]);
        float4 xa, xb;
        if (LAYER == 0) {
            xa = (ca.x < NUM_USERS) ? __ldg(&ue[ca.x * D4 + l])
                                    : __ldg(&ie[(ca.x - NUM_USERS) * D4 + l]);
            xb = (cb.x < NUM_USERS) ? __ldg(&ue[cb.x * D4 + l])
                                    : __ldg(&ie[(cb.x - NUM_USERS) * D4 + l]);
        } else {
            xa = __ldg(&src[ca.x * D4 + l]);
            xb = __ldg(&src[cb.x * D4 + l]);
        }
        float va = __int_as_float(ca.y), vb = __int_as_float(cb.y);
        acc.x += va * xa.x + vb * xb.x;
        acc.y += va * xa.y + vb * xb.y;
        acc.z += va * xa.z + vb * xb.z;
        acc.w += va * xa.w + vb * xb.w;
    }
    if (j < end) {
        int2 ca = __ldg(&g_cva[j]);
        float4 xa;
        if (LAYER == 0) {
            xa = (ca.x < NUM_USERS) ? __ldg(&ue[ca.x * D4 + l])
                                    : __ldg(&ie[(ca.x - NUM_USERS) * D4 + l]);
        } else {
            xa = __ldg(&src[ca.x * D4 + l]);
        }
        float va = __int_as_float(ca.y);
        acc.x += va * xa.x; acc.y += va * xa.y;
        acc.z += va * xa.z; acc.w += va * xa.w;
    }

    float4* __restrict__ dst = (LAYER == 0) ? g_X1 : (LAYER == 1) ? g_X2 : g_X3;
    dst[r * D4 + l] = acc;
}

// ---------------------------------------------------------------------------
// Readout: out[b] = dot((X1+X2+X3)[u], (X1+X2+X3)[i+NU]) / 9
// ---------------------------------------------------------------------------
__global__ void dot_kernel(const int* __restrict__ uid,
                           const int* __restrict__ iid,
                           float* __restrict__ out) {
    int gid = blockIdx.x * blockDim.x + threadIdx.x;
    int b = gid >> 4;
    int l = gid & 15;
    if (b >= BATCH) return;

    unsigned ur = (unsigned)__ldg(&uid[b]);
    unsigned ir = (unsigned)__ldg(&iid[b]) + NUM_USERS;
    float d = 0.f;

    if (ur < NTOT && ir < NTOT) {
        int uo = (int)ur * D4 + l;
        int io = (int)ir * D4 + l;
        float4 a1 = g_X1[uo], a2 = g_X2[uo], a3 = g_X3[uo];
        float4 b1 = g_X1[io], b2 = g_X2[io], b3 = g_X3[io];
        float fux = a1.x + a2.x + a3.x, fuy = a1.y + a2.y + a3.y;
        float fuz = a1.z + a2.z + a3.z, fuw = a1.w + a2.w + a3.w;
        float fix = b1.x + b2.x + b3.x, fiy = b1.y + b2.y + b3.y;
        float fiz = b1.z + b2.z + b3.z, fiw = b1.w + b2.w + b3.w;
        d = fux * fix + fuy * fiy + fuz * fiz + fuw * fiw;
    }

    #pragma unroll
    for (int off = 8; off > 0; off >>= 1)
        d += __shfl_down_sync(0xffffffffu, d, off, 16);

    if (l == 0) out[b] = d * (1.0f / 9.0f);
}

// ---------------------------------------------------------------------------
extern "C" void kernel_launch(void* const* d_in, const int* in_sizes, int n_in,
                              void* d_out, int out_size) {
    const float4* user_emb = (const float4*)d_in[0];   // [100000,64] f32
    const float4* item_emb = (const float4*)d_in[1];   // [50000,64]  f32
    const float*  vals     = (const float*) d_in[2];   // [2E] f32
    const int*    rows     = (const int*)   d_in[3];   // [2E] i32
    const int*    cols     = (const int*)   d_in[4];   // [2E] i32
    const int*    uid      = (const int*)   d_in[5];   // [4096] i32
    const int*    iid      = (const int*)   d_in[6];   // [4096] i32
    float*        out      = (float*)d_out;            // [4096] f32

    const int ne = in_sizes[2];

    zero_kernel<<<(NTOT + 255) / 256, 256>>>();
    mark_kernel<<<(BATCH + 255) / 256, 256>>>(uid, iid);

    int eblocks = (ne + 255) / 256;
    degree_kernel<<<eblocks, 256>>>(rows, ne);
    scan_reduce_kernel<<<NBLK, SCAN_B>>>();
    scan_partials_kernel<<<1, 1024>>>();
    scan_final_kernel<<<NBLK, SCAN_B>>>();
    scatter_kernel<<<eblocks, 256>>>(vals, rows, cols, ne);

    int t_dense = NTOT * D4;
    spmm_csr_kernel<0><<<(t_dense + 255) / 256, 256>>>(user_emb, item_emb);
    spmm_csr_kernel<1><<<(t_dense + 255) / 256, 256>>>(user_emb, item_emb);
    spmm_csr_kernel<2><<<(MAXROWS * 16 + 255) / 256, 256>>>(user_emb, item_emb);

    dot_kernel<<<(BATCH * 16 + 255) / 256, 256>>>(uid, iid, out);
}

// round 11
// speedup vs baseline: 1.2506x; 1.0017x over previous
#include <cuda_runtime.h>
#include <cstdint>

// XSimGCL / LightGCN on GB300 (sm_103a) — compact CSR.
// R11: exploit symmetrized edge layout (rows=[u,v+NU], cols=[v+NU,u],
// vals[e]==vals[e+2M]) -> build CSR from base pairs only (halves index reads);
// fuse mark into degree; streaming cache hints on single-use edge traffic.

#define NUM_USERS 100000
#define NUM_ITEMS 50000
#define NTOT      (NUM_USERS + NUM_ITEMS)   // 150000
#define D4        16                        // float4s per 64-dim row
#define BATCH     4096
#define MAXE      4200000                   // >= 2*NUM_BASE_EDGES
#define MAXROWS   8192
#define SCAN_B    256
#define NBLK      ((NTOT + SCAN_B - 1) / SCAN_B)   // 586

// Scratch (allocation-free rule: __device__ globals; device-code refs only).
__device__ float4   g_X1[NTOT * D4];
__device__ float4   g_X2[NTOT * D4];
__device__ float4   g_X3[NTOT * D4];
__device__ int      g_cnt[NTOT];
__device__ int      g_off[NTOT + 1];
__device__ int      g_pos[NTOT];
__device__ int      g_part[1024];           // >= NBLK
__device__ int2     g_cva[MAXE];            // packed {col, float_as_int(val)}
__device__ unsigned g_bitmap [(NTOT + 31) / 32];   // flagged (layer-3 outputs)
__device__ unsigned g_bitmap2[(NTOT + 31) / 32];   // flagged ∪ N(flagged)
__device__ int      g_rowlist[MAXROWS];
__device__ int      g_nrows;

// ---------------------------------------------------------------------------
__global__ void zero_kernel() {
    int i = blockIdx.x * blockDim.x + threadIdx.x;
    if (i < NTOT) g_cnt[i] = 0;
    if (i < (NTOT + 31) / 32) { g_bitmap[i] = 0u; g_bitmap2[i] = 0u; }
    if (i == 0) g_nrows = 0;
}

// Fused: degree histogram from BASE pairs (u -> cnt[u]++, cnt[v+NU]++)
// + mark flagged rows (layer-3 outputs) + compact unique rows + seed bitmap2.
__global__ void degree_mark_kernel(const int* __restrict__ rows,  // u  = rows[0:nb)
                                   const int* __restrict__ cols,  // v' = cols[... ] NOTE: cols[0:nb) = v+NU
                                   const int* __restrict__ uid,
                                   const int* __restrict__ iid,
                                   int nb) {
    int i = blockIdx.x * blockDim.x + threadIdx.x;
    if (i < nb) {
        unsigned u = (unsigned)__ldcs(&rows[i]);       // user row
        unsigned w = (unsigned)__ldcs(&cols[i]);       // item row (already +NU)
        if (u < NTOT) atomicAdd(&g_cnt[u], 1);
        if (w < NTOT) atomicAdd(&g_cnt[w], 1);
    }
    if (i < BATCH) {
        unsigned r[2];
        r[0] = (unsigned)__ldg(&uid[i]);
        r[1] = (unsigned)__ldg(&iid[i]) + NUM_USERS;
        #pragma unroll
        for (int k = 0; k < 2; k++) {
            if (r[k] < NTOT) {
                unsigned bit = 1u << (r[k] & 31);
                unsigned old = atomicOr(&g_bitmap[r[k] >> 5], bit);
                atomicOr(&g_bitmap2[r[k] >> 5], bit);
                if (!(old & bit)) {
                    int p = atomicAdd(&g_nrows, 1);
                    if (p < MAXROWS) g_rowlist[p] = (int)r[k];
                }
            }
        }
    }
}

// ---------------------------------------------------------------------------
// 3-pass parallel exclusive scan over g_cnt -> g_off / g_pos.
// ---------------------------------------------------------------------------
__global__ void scan_reduce_kernel() {
    __shared__ int sh[SCAN_B];
    int idx = blockIdx.x * SCAN_B + threadIdx.x;
    sh[threadIdx.x] = (idx < NTOT) ? g_cnt[idx] : 0;
    __syncthreads();
    #pragma unroll
    for (int off = SCAN_B / 2; off > 0; off >>= 1) {
        if (threadIdx.x < off) sh[threadIdx.x] += sh[threadIdx.x + off];
        __syncthreads();
    }
    if (threadIdx.x == 0) g_part[blockIdx.x] = sh[0];
}

__global__ void scan_partials_kernel() {
    __shared__ int sh[1024];
    int tid = threadIdx.x;
    int v = (tid < NBLK) ? g_part[tid] : 0;
    sh[tid] = v;
    __syncthreads();
    for (int off = 1; off < 1024; off <<= 1) {
        int t = (tid >= off) ? sh[tid - off] : 0;
        __syncthreads();
        sh[tid] += t;
        __syncthreads();
    }
    if (tid < NBLK) g_part[tid] = sh[tid] - v;   // exclusive
    if (tid == NBLK - 1) g_off[NTOT] = sh[tid];
}

__global__ void scan_final_kernel() {
    __shared__ int sh[SCAN_B];
    int idx = blockIdx.x * SCAN_B + threadIdx.x;
    int c = (idx < NTOT) ? g_cnt[idx] : 0;
    sh[threadIdx.x] = c;
    __syncthreads();
    #pragma unroll
    for (int off = 1; off < SCAN_B; off <<= 1) {
        int t = (threadIdx.x >= off) ? sh[threadIdx.x - off] : 0;
        __syncthreads();
        sh[threadIdx.x] += t;
        __syncthreads();
    }
    if (idx < NTOT) {
        int off = g_part[blockIdx.x] + sh[threadIdx.x] - c;   // exclusive
        g_off[idx] = off;
        g_pos[idx] = off;
    }
}

// ---------------------------------------------------------------------------
// Scatter BOTH directed edges per base pair (vals symmetric by construction).
// Streaming hints: edge reads/writes are single-use, keep them out of L2's
// resident set (X arrays). Fused bitmap2 marking for flagged endpoints.
// ---------------------------------------------------------------------------
__global__ void scatter_kernel(const float* __restrict__ vals,
                               const int*   __restrict__ rows,
                               const int*   __restrict__ cols,
                               int nb) {
    int i = blockIdx.x * blockDim.x + threadIdx.x;
    if (i >= nb) return;
    unsigned u = (unsigned)__ldcs(&rows[i]);   // user row
    unsigned w = (unsigned)__ldcs(&cols[i]);   // item row (already +NU)
    float    v = __ldcs(&vals[i]);
    int vbits = __float_as_int(v);

    if (u < NTOT) {                            // edge u -> w
        int p = atomicAdd(&g_pos[u], 1);
        if (p < MAXE) __stcs(&g_cva[p], make_int2((int)w, vbits));
        if ((g_bitmap[u >> 5] >> (u & 31)) & 1u)
            if (w < NTOT) atomicOr(&g_bitmap2[w >> 5], 1u << (w & 31));
    }
    if (w < NTOT) {                            // edge w -> u
        int p = atomicAdd(&g_pos[w], 1);
        if (p < MAXE) __stcs(&g_cva[p], make_int2((int)u, vbits));
        if ((g_bitmap[w >> 5] >> (w & 31)) & 1u)
            if (u < NTOT) atomicOr(&g_bitmap2[u >> 5], 1u << (u & 31));
    }
}

// ---------------------------------------------------------------------------
// CSR SpMM: one 16-lane group per row, register accumulate, single store.
// LAYER 0: src = (user_emb|item_emb) direct, dst = X1 (all rows)
// LAYER 1: X1 -> X2, only rows in bitmap2 (flagged ∪ N(flagged))
// LAYER 2: X2 -> X3, only compacted g_rowlist
// ---------------------------------------------------------------------------
template <int LAYER>
__global__ void __launch_bounds__(256)
spmm_csr_kernel(const float4* __restrict__ ue,
                const float4* __restrict__ ie) {
    int gid = blockIdx.x * blockDim.x + threadIdx.x;
    int g = gid >> 4;
    int l = gid & 15;

    int r;
    if (LAYER == 2) {
        if (g >= g_nrows) return;
        r = g_rowlist[g];
    } else {
        if (g >= NTOT) return;
        r = g;
        if (LAYER == 1) {
            if (!((g_bitmap2[r >> 5] >> (r & 31)) & 1u)) return;
        }
    }

    int beg = __ldg(&g_off[r]);
    int end = __ldg(&g_off[r + 1]);

    const float4* __restrict__ src = (LAYER == 1) ? g_X1 : g_X2;  // unused L0
    float4 acc = make_float4(0.f, 0.f, 0.f, 0.f);

    int j = beg;
    for (; j + 1 < end; j += 2) {       // 2 gathers in flight per group
        int2 ca = __ldcs(&g_cva[j]);
        int2 cb = __ldcs(&g_cva[j + 1]);
        float4 xa, xb;
        if (LAYER == 0) {
            xa = (ca.x < NUM_USERS) ? __ldg(&ue[ca.x * D4 + l])
                                    : __ldg(&ie[(ca.x - NUM_USERS) * D4 + l]);
            xb = (cb.x < NUM_USERS) ? __ldg(&ue[cb.x * D4 + l])
                                    : __ldg(&ie[(cb.x - NUM_USERS) * D4 + l]);
        } else {
            xa = __ldg(&src[ca.x * D4 + l]);
            xb = __ldg(&src[cb.x * D4 + l]);
        }
        float va = __int_as_float(ca.y), vb = __int_as_float(cb.y);
        acc.x += va * xa.x + vb * xb.x;
        acc.y += va * xa.y + vb * xb.y;
        acc.z += va * xa.z + vb * xb.z;
        acc.w += va * xa.w + vb * xb.w;
    }
    if (j < end) {
        int2 ca = __ldcs(&g_cva[j]);
        float4 xa;
        if (LAYER == 0) {
            xa = (ca.x < NUM_USERS) ? __ldg(&ue[ca.x * D4 + l])
                                    : __ldg(&ie[(ca.x - NUM_USERS) * D4 + l]);
        } else {
            xa = __ldg(&src[ca.x * D4 + l]);
        }
        float va = __int_as_float(ca.y);
        acc.x += va * xa.x; acc.y += va * xa.y;
        acc.z += va * xa.z; acc.w += va * xa.w;
    }

    float4* __restrict__ dst = (LAYER == 0) ? g_X1 : (LAYER == 1) ? g_X2 : g_X3;
    dst[r * D4 + l] = acc;
}

// ---------------------------------------------------------------------------
// Readout: out[b] = dot((X1+X2+X3)[u], (X1+X2+X3)[i+NU]) / 9
// ---------------------------------------------------------------------------
__global__ void dot_kernel(const int* __restrict__ uid,
                           const int* __restrict__ iid,
                           float* __restrict__ out) {
    int gid = blockIdx.x * blockDim.x + threadIdx.x;
    int b = gid >> 4;
    int l = gid & 15;
    if (b >= BATCH) return;

    unsigned ur = (unsigned)__ldg(&uid[b]);
    unsigned ir = (unsigned)__ldg(&iid[b]) + NUM_USERS;
    float d = 0.f;

    if (ur < NTOT && ir < NTOT) {
        int uo = (int)ur * D4 + l;
        int io = (int)ir * D4 + l;
        float4 a1 = g_X1[uo], a2 = g_X2[uo], a3 = g_X3[uo];
        float4 b1 = g_X1[io], b2 = g_X2[io], b3 = g_X3[io];
        float fux = a1.x + a2.x + a3.x, fuy = a1.y + a2.y + a3.y;
        float fuz = a1.z + a2.z + a3.z, fuw = a1.w + a2.w + a3.w;
        float fix = b1.x + b2.x + b3.x, fiy = b1.y + b2.y + b3.y;
        float fiz = b1.z + b2.z + b3.z, fiw = b1.w + b2.w + b3.w;
        d = fux * fix + fuy * fiy + fuz * fiz + fuw * fiw;
    }

    #pragma unroll
    for (int off = 8; off > 0; off >>= 1)
        d += __shfl_down_sync(0xffffffffu, d, off, 16);

    if (l == 0) out[b] = d * (1.0f / 9.0f);
}

// ---------------------------------------------------------------------------
extern "C" void kernel_launch(void* const* d_in, const int* in_sizes, int n_in,
                              void* d_out, int out_size) {
    const float4* user_emb = (const float4*)d_in[0];   // [100000,64] f32
    const float4* item_emb = (const float4*)d_in[1];   // [50000,64]  f32
    const float*  vals     = (const float*) d_in[2];   // [2E] f32
    const int*    rows     = (const int*)   d_in[3];   // [2E] i32: [u, v+NU]
    const int*    cols     = (const int*)   d_in[4];   // [2E] i32: [v+NU, u]
    const int*    uid      = (const int*)   d_in[5];   // [4096] i32
    const int*    iid      = (const int*)   d_in[6];   // [4096] i32
    float*        out      = (float*)d_out;            // [4096] f32

    const int ne = in_sizes[2];
    const int nb = ne / 2;                  // base (undirected) pairs

    zero_kernel<<<(NTOT + 255) / 256, 256>>>();

    int bblocks = (nb + 255) / 256;
    degree_mark_kernel<<<bblocks, 256>>>(rows, cols, uid, iid, nb);
    scan_reduce_kernel<<<NBLK, SCAN_B>>>();
    scan_partials_kernel<<<1, 1024>>>();
    scan_final_kernel<<<NBLK, SCAN_B>>>();
    scatter_kernel<<<bblocks, 256>>>(vals, rows, cols, nb);

    int t_dense = NTOT * D4;
    spmm_csr_kernel<0><<<(t_dense + 255) / 256, 256>>>(user_emb, item_emb);
    spmm_csr_kernel<1><<<(t_dense + 255) / 256, 256>>>(user_emb, item_emb);
    spmm_csr_kernel<2><<<(MAXROWS * 16 + 255) / 256, 256>>>(user_emb, item_emb);

    dot_kernel<<<(BATCH * 16 + 255) / 256, 256>>>(uid, iid, out);
}